// round 11
// baseline (speedup 1.0000x reference)
#include <cuda_runtime.h>
#include <math.h>
#include <stdint.h>

#define BB 8
#define NN 1024
#define DIM 192
#define HEADS 16
#define DHEAD 64
#define INNER 1024
#define TOK (BB*NN)       // 8192
#define QKVN (3*INNER)    // 3072

// Scratch (allocation-free rule: __device__ globals)
__device__ float g_h[TOK*DIM];
__device__ float g_qkv[(size_t)TOK*QKVN];
__device__ float g_attn[(size_t)TOK*INNER];
__device__ float g_wqkv[DIM*QKVN];
__device__ float g_wout[INNER*DIM];

__device__ __forceinline__ uint32_t f2tf(float x){
    uint32_t u; asm("cvt.rna.tf32.f32 %0, %1;" : "=r"(u) : "f"(x)); return u;
}
__device__ __forceinline__ float ex2(float x){
    float y; asm("ex2.approx.f32 %0, %1;" : "=f"(y) : "f"(x)); return y;
}

// D += A@B, m16n8k8 tf32. c0=[g][2t], c1=[g][2t+1], c2=[g+8][2t], c3=[g+8][2t+1]
__device__ __forceinline__ void mma_tf32(float* c, uint32_t a0, uint32_t a1, uint32_t a2, uint32_t a3,
                                         uint32_t b0, uint32_t b1){
    asm volatile("mma.sync.aligned.m16n8k8.row.col.f32.tf32.tf32.f32 "
        "{%0,%1,%2,%3}, {%4,%5,%6,%7}, {%8,%9}, {%0,%1,%2,%3};"
        : "+f"(c[0]), "+f"(c[1]), "+f"(c[2]), "+f"(c[3])
        : "r"(a0), "r"(a1), "r"(a2), "r"(a3), "r"(b0), "r"(b1));
}

__device__ __forceinline__ void ldsm4(uint32_t* r, uint32_t saddr){
    asm volatile("ldmatrix.sync.aligned.m8n8.x4.shared.b16 {%0,%1,%2,%3}, [%4];"
        : "=r"(r[0]), "=r"(r[1]), "=r"(r[2]), "=r"(r[3]) : "r"(saddr));
}

__device__ __forceinline__ void cpa16(uint32_t dst, const void* src){
    asm volatile("cp.async.cg.shared.global [%0], [%1], 16;" :: "r"(dst), "l"(src));
}
__device__ __forceinline__ void cp_commit(){ asm volatile("cp.async.commit_group;"); }
template<int N> __device__ __forceinline__ void cp_wait(){
    asm volatile("cp.async.wait_group %0;" :: "n"(N));
}

// ---------------------------------------------------------------------------
// Elementwise fp32 -> tf32-rounded fp32 bits (for weights)
// ---------------------------------------------------------------------------
__global__ __launch_bounds__(256)
void cvt_tf32_kernel(const float* __restrict__ src, float* __restrict__ dst, int n){
    for (int i = blockIdx.x*256 + threadIdx.x; i < n; i += gridDim.x*256)
        dst[i] = __uint_as_float(f2tf(src[i]));
}

// ---------------------------------------------------------------------------
// LayerNorm + adaLN modulation: one warp per token; output tf32-rounded
// ---------------------------------------------------------------------------
__global__ __launch_bounds__(256)
void ln_mod_kernel(const float* __restrict__ x,
                   const float* __restrict__ shift,
                   const float* __restrict__ scale,
                   const float* __restrict__ w,
                   const float* __restrict__ bpar) {
    int warp = threadIdx.x >> 5;
    int lane = threadIdx.x & 31;
    int t = blockIdx.x * 8 + warp;
    const float* xr = x + (size_t)t * DIM;
    float v[6];
    float s = 0.f;
#pragma unroll
    for (int q = 0; q < 6; q++) { v[q] = xr[lane + q*32]; s += v[q]; }
#pragma unroll
    for (int o = 16; o; o >>= 1) s += __shfl_xor_sync(0xffffffffu, s, o);
    float mu = s * (1.f/DIM);
    float vs = 0.f;
#pragma unroll
    for (int q = 0; q < 6; q++) { float d = v[q]-mu; vs += d*d; }
#pragma unroll
    for (int o = 16; o; o >>= 1) vs += __shfl_xor_sync(0xffffffffu, vs, o);
    float rstd = rsqrtf(vs*(1.f/DIM) + 1e-5f);
    int bi = t >> 10;
#pragma unroll
    for (int q = 0; q < 6; q++) {
        int d = lane + q*32;
        float hn = (v[q]-mu)*rstd*w[d] + bpar[d];
        hn = hn * (1.f + scale[bi*DIM + d]) + shift[bi*DIM + d];
        g_h[(size_t)t*DIM + d] = __uint_as_float(f2tf(hn));
    }
}

// ---------------------------------------------------------------------------
// tf32 TC GEMM (mma.sync), templated tile. BK=32, 256 thr.
// ---------------------------------------------------------------------------
#define GA_STR 36

template<int BM, int BN, int WR, int WC>
__global__ __launch_bounds__(256, 2)
void gemm_tc(const float* __restrict__ A, const float* __restrict__ Bm,
             const float* __restrict__ bias, float* __restrict__ C,
             int M, int Nn, int K){
    constexpr int NFR   = (BN/WC)/8;
    constexpr int AIT   = BM*8/256;
    constexpr int BIT   = BN*8/256;
    constexpr int BQ    = BN/4;
    constexpr int B_STR = BN + 8;
    constexpr int ABUF  = BM*GA_STR;
    constexpr int BBUF  = 32*B_STR;
    extern __shared__ uint32_t smg[];
    uint32_t* As = smg;
    uint32_t* Bs = smg + 2*ABUF;
    int m0 = blockIdx.y*BM, n0 = blockIdx.x*BN;
    int tid = threadIdx.x;
    int w = tid>>5, lane = tid&31;
    int g = lane>>2, t = lane&3;
    int wm = w / WC, wn = w % WC;
    uint32_t as_sh = (uint32_t)__cvta_generic_to_shared(As);
    uint32_t bs_sh = (uint32_t)__cvta_generic_to_shared(Bs);
    int a_sub = ((lane>>3)&1)*8 + (lane&7);
    int a_kh  = (lane>>4)*4;

    float acc[2][NFR][4] = {};

    auto issue = [&](int kt, int buf){
#pragma unroll
        for (int i = 0; i < AIT; i++){
            int fid = tid + i*256; int r = fid>>3, cq = fid&7;
            cpa16(as_sh + (uint32_t)(buf*ABUF + r*GA_STR + cq*4)*4,
                  &A[(size_t)(m0+r)*K + kt + cq*4]);
        }
#pragma unroll
        for (int i = 0; i < BIT; i++){
            int fid = tid + i*256; int r = fid/BQ, cq = fid%BQ;
            cpa16(bs_sh + (uint32_t)(buf*BBUF + r*B_STR + cq*4)*4,
                  &Bm[(size_t)(kt+r)*Nn + n0 + cq*4]);
        }
        cp_commit();
    };

    issue(0, 0);
    int nt = K/32;
    for (int it = 0; it < nt; it++){
        int buf = it & 1;
        cp_wait<0>();
        __syncthreads();
        if (it + 1 < nt) issue((it+1)*32, buf^1);
#pragma unroll
        for (int ks = 0; ks < 4; ks++){
            int k0 = ks*8;
            uint32_t af[2][4];
#pragma unroll
            for (int mf = 0; mf < 2; mf++){
                int row = wm*32 + mf*16 + a_sub;
                ldsm4(af[mf], as_sh + (uint32_t)(buf*ABUF + row*GA_STR + k0 + a_kh)*4);
            }
#pragma unroll
            for (int nf = 0; nf < NFR; nf++){
                int col = wn*(BN/WC) + nf*8 + g;
                uint32_t b0 = Bs[buf*BBUF + (k0+t)*B_STR + col];
                uint32_t b1 = Bs[buf*BBUF + (k0+4+t)*B_STR + col];
                mma_tf32(acc[0][nf], af[0][0],af[0][1],af[0][2],af[0][3], b0,b1);
                mma_tf32(acc[1][nf], af[1][0],af[1][1],af[1][2],af[1][3], b0,b1);
            }
        }
        __syncthreads();
    }
#pragma unroll
    for (int mf = 0; mf < 2; mf++){
#pragma unroll
        for (int nf = 0; nf < NFR; nf++){
            int row = m0 + wm*32 + mf*16 + g;
            int col = n0 + wn*(BN/WC) + nf*8 + t*2;
            if (bias){
                float bx = bias[col], by = bias[col+1];
                *(float2*)&C[(size_t)row*Nn + col] =
                    make_float2(acc[mf][nf][0]+bx, acc[mf][nf][1]+by);
                *(float2*)&C[(size_t)(row+8)*Nn + col] =
                    make_float2(acc[mf][nf][2]+bx, acc[mf][nf][3]+by);
            } else {
                *(uint2*)&C[(size_t)row*Nn + col] =
                    make_uint2(f2tf(acc[mf][nf][0]), f2tf(acc[mf][nf][1]));
                *(uint2*)&C[(size_t)(row+8)*Nn + col] =
                    make_uint2(f2tf(acc[mf][nf][2]), f2tf(acc[mf][nf][3]));
            }
        }
    }
}

// ---------------------------------------------------------------------------
// Flash attention, tf32 mma.sync. 256 thr; warp owns 32 q-rows (2 m-frags);
// CTA covers 256 q-rows. Q persistent in smem (ldsm per tile); P in its own
// smem region; K/V cp.async double-buffered. Base-2 softmax.
// ---------------------------------------------------------------------------
#define AT_STR 68
#define V_STR  72
#define QROWS 256
#define KBUF (64*AT_STR)
#define VBUF (64*V_STR)
#define ATTN_SMEM_WORDS (2*QROWS*AT_STR + 2*KBUF + 2*VBUF)
#define ATTN_SMEM_BYTES (ATTN_SMEM_WORDS*4)   // 210944
#define QSCALE 0.18033688f   // 0.125 * log2(e)

__global__ __launch_bounds__(256, 1)
void attn_tc(const float* __restrict__ qkv, float* __restrict__ out){
    extern __shared__ uint32_t sm[];
    uint32_t* Qs = sm;                     // 256 x AT_STR (persistent Q)
    uint32_t* Ps = sm + QROWS*AT_STR;      // 256 x AT_STR (P per tile)
    uint32_t* Ks = Ps + QROWS*AT_STR;      // 2 buffers
    uint32_t* Vs = Ks + 2*KBUF;            // 2 buffers

    int qt = blockIdx.x, bh = blockIdx.y;  // qt: 0..3 (256-row tiles)
    int b = bh>>4, h = bh&15;
    int tid = threadIdx.x, w = tid>>5, lane = tid&31;
    int g = lane>>2, t = lane&3;
    const float* base = qkv + (size_t)b*NN*QKVN + h*DHEAD;

    uint32_t qs_sh = (uint32_t)__cvta_generic_to_shared(Qs);
    uint32_t ps_sh = (uint32_t)__cvta_generic_to_shared(Ps);
    uint32_t ks_sh = (uint32_t)__cvta_generic_to_shared(Ks);
    uint32_t vs_sh = (uint32_t)__cvta_generic_to_shared(Vs);
    int sub_row = ((lane>>3)&1)*8 + (lane&7);
    int a_kh = (lane>>4)*4;
    uint32_t q_base[2], p_base[2];
#pragma unroll
    for (int mf = 0; mf < 2; mf++){
        int ar = w*32 + mf*16 + sub_row;
        q_base[mf] = qs_sh + (uint32_t)(ar*AT_STR + a_kh)*4;
        p_base[mf] = ps_sh + (uint32_t)(ar*AT_STR + a_kh)*4;
    }
    int kb_row = ((lane>>4)<<3) + (lane&7);
    uint32_t kb_off = (uint32_t)(kb_row*AT_STR + ((lane>>3)&1)*4)*4;

    // Q staging (256 rows), base-2 scale folded, re-rounded to tf32
#pragma unroll
    for (int i = 0; i < 16; i++){
        int fid = tid + i*256;
        int r = fid>>4, cq = fid&15;
        float4 v = *(const float4*)&base[(size_t)(qt*QROWS+r)*QKVN + cq*4];
        *(uint4*)&Qs[r*AT_STR + cq*4] = make_uint4(
            f2tf(v.x*QSCALE), f2tf(v.y*QSCALE), f2tf(v.z*QSCALE), f2tf(v.w*QSCALE));
    }

    auto issue = [&](int kt, int buf){
#pragma unroll
        for (int i = 0; i < 4; i++){
            int fid = tid + i*256;
            int r = fid>>4, cq = fid&15;
            const float* kr = &base[(size_t)(kt*64+r)*QKVN + INNER + cq*4];
            cpa16(ks_sh + (uint32_t)(buf*KBUF + r*AT_STR + cq*4)*4, kr);
            cpa16(vs_sh + (uint32_t)(buf*VBUF + r*V_STR  + cq*4)*4, kr + INNER);
        }
        cp_commit();
    };

    float o[2][8][4] = {};
    float mi[2][2], li[2][2] = {};
    mi[0][0] = mi[0][1] = mi[1][0] = mi[1][1] = -INFINITY;

    issue(0, 0);
    __syncthreads();   // Q staging visible (also covers first ldsm below)

    for (int kt = 0; kt < 16; kt++){
        int buf = kt & 1;
        cp_wait<0>();
        __syncthreads();
        if (kt + 1 < 16) issue(kt+1, buf^1);

        // S = Q @ K^T  (2 m-frags x 8 key-groups)
        float s[2][8][4] = {};
        uint32_t kbb = ks_sh + (uint32_t)(buf*KBUF)*4 + kb_off;
#pragma unroll
        for (int ks = 0; ks < 8; ks++){
            uint32_t qa[2][4];
            ldsm4(qa[0], q_base[0] + ks*32);
            ldsm4(qa[1], q_base[1] + ks*32);
#pragma unroll
            for (int nfp = 0; nfp < 4; nfp++){
                uint32_t kb[4];
                ldsm4(kb, kbb + (uint32_t)(nfp*16*AT_STR)*4 + ks*32);
                mma_tf32(s[0][2*nfp],   qa[0][0],qa[0][1],qa[0][2],qa[0][3], kb[0], kb[1]);
                mma_tf32(s[0][2*nfp+1], qa[0][0],qa[0][1],qa[0][2],qa[0][3], kb[2], kb[3]);
                mma_tf32(s[1][2*nfp],   qa[1][0],qa[1][1],qa[1][2],qa[1][3], kb[0], kb[1]);
                mma_tf32(s[1][2*nfp+1], qa[1][0],qa[1][1],qa[1][2],qa[1][3], kb[2], kb[3]);
            }
        }

        __syncwarp();      // prior PV ldsm reads of Ps done (warp-private rows)
#pragma unroll
        for (int mf = 0; mf < 2; mf++){
            // Online softmax, base 2 (quad reduce xor 1,2)
            float mx0 = -INFINITY, mx1 = -INFINITY;
#pragma unroll
            for (int nf = 0; nf < 8; nf++){
                mx0 = fmaxf(mx0, fmaxf(s[mf][nf][0], s[mf][nf][1]));
                mx1 = fmaxf(mx1, fmaxf(s[mf][nf][2], s[mf][nf][3]));
            }
            mx0 = fmaxf(mx0, __shfl_xor_sync(0xffffffffu, mx0, 1));
            mx0 = fmaxf(mx0, __shfl_xor_sync(0xffffffffu, mx0, 2));
            mx1 = fmaxf(mx1, __shfl_xor_sync(0xffffffffu, mx1, 1));
            mx1 = fmaxf(mx1, __shfl_xor_sync(0xffffffffu, mx1, 2));
            float mn0 = fmaxf(mi[mf][0], mx0), mn1 = fmaxf(mi[mf][1], mx1);
            float sc0 = ex2(mi[mf][0] - mn0), sc1 = ex2(mi[mf][1] - mn1);
            mi[mf][0] = mn0; mi[mf][1] = mn1;

            int prow = w*32 + mf*16 + g;
            float sum0 = 0.f, sum1 = 0.f;
#pragma unroll
            for (int nf = 0; nf < 8; nf++){
                float p0 = ex2(s[mf][nf][0] - mn0), p1 = ex2(s[mf][nf][1] - mn0);
                float p2 = ex2(s[mf][nf][2] - mn1), p3 = ex2(s[mf][nf][3] - mn1);
                sum0 += p0 + p1; sum1 += p2 + p3;
                int col = nf*8 + t*2;
                *(uint2*)&Ps[prow*AT_STR + col]     = make_uint2(f2tf(p0), f2tf(p1));
                *(uint2*)&Ps[(prow+8)*AT_STR + col] = make_uint2(f2tf(p2), f2tf(p3));
            }
            sum0 += __shfl_xor_sync(0xffffffffu, sum0, 1);
            sum0 += __shfl_xor_sync(0xffffffffu, sum0, 2);
            sum1 += __shfl_xor_sync(0xffffffffu, sum1, 1);
            sum1 += __shfl_xor_sync(0xffffffffu, sum1, 2);
            li[mf][0] = li[mf][0]*sc0 + sum0;
            li[mf][1] = li[mf][1]*sc1 + sum1;
#pragma unroll
            for (int nf = 0; nf < 8; nf++){
                o[mf][nf][0] *= sc0; o[mf][nf][1] *= sc0;
                o[mf][nf][2] *= sc1; o[mf][nf][3] *= sc1;
            }
        }
        __syncwarp();      // Ps visible warp-wide

        // O += P @ V  (V b-frags shared across both m-frags)
#pragma unroll
        for (int ks = 0; ks < 8; ks++){
            int k0 = ks*8;
            uint32_t pa[2][4];
            ldsm4(pa[0], p_base[0] + ks*32);
            ldsm4(pa[1], p_base[1] + ks*32);
#pragma unroll
            for (int nf = 0; nf < 8; nf++){
                int d0 = nf*8 + g;
                uint32_t b0 = Vs[buf*VBUF + (k0+t)*V_STR + d0];
                uint32_t b1 = Vs[buf*VBUF + (k0+4+t)*V_STR + d0];
                mma_tf32(o[0][nf], pa[0][0],pa[0][1],pa[0][2],pa[0][3], b0, b1);
                mma_tf32(o[1][nf], pa[1][0],pa[1][1],pa[1][2],pa[1][3], b0, b1);
            }
        }
    }

    // Epilogue: tf32-round for the out-projection GEMM
#pragma unroll
    for (int mf = 0; mf < 2; mf++){
        float inv0 = 1.f/li[mf][0], inv1 = 1.f/li[mf][1];
        int row = qt*QROWS + w*32 + mf*16 + g;
#pragma unroll
        for (int nf = 0; nf < 8; nf++){
            int col = h*DHEAD + nf*8 + t*2;
            *(uint2*)&out[((size_t)(b*NN+row))*INNER + col]   =
                make_uint2(f2tf(o[mf][nf][0]*inv0), f2tf(o[mf][nf][1]*inv0));
            *(uint2*)&out[((size_t)(b*NN+row+8))*INNER + col] =
                make_uint2(f2tf(o[mf][nf][2]*inv1), f2tf(o[mf][nf][3]*inv1));
        }
    }
}

// ---------------------------------------------------------------------------
extern "C" void kernel_launch(void* const* d_in, const int* in_sizes, int n_in,
                              void* d_out, int out_size) {
    const float* x      = (const float*)d_in[0];
    const float* shift  = (const float*)d_in[1];
    const float* scale  = (const float*)d_in[2];
    const float* norm_w = (const float*)d_in[3];
    const float* norm_b = (const float*)d_in[4];
    const float* w_qkv  = (const float*)d_in[5];
    const float* w_out  = (const float*)d_in[6];
    const float* b_out  = (const float*)d_in[7];
    float* out = (float*)d_out;

    float *hp, *qkvp, *attnp, *wqp, *wop;
    cudaGetSymbolAddress((void**)&hp,    g_h);
    cudaGetSymbolAddress((void**)&qkvp,  g_qkv);
    cudaGetSymbolAddress((void**)&attnp, g_attn);
    cudaGetSymbolAddress((void**)&wqp,   g_wqkv);
    cudaGetSymbolAddress((void**)&wop,   g_wout);

    const int gsm_qkv = (2*128*GA_STR + 2*32*(128+8))*4;   // 71680
    const int gsm_out = (2*64*GA_STR  + 2*32*(64+8))*4;    // 36864
    cudaFuncSetAttribute((gemm_tc<128,128,4,2>),
                         cudaFuncAttributeMaxDynamicSharedMemorySize, gsm_qkv);
    cudaFuncSetAttribute((gemm_tc<64,64,2,4>),
                         cudaFuncAttributeMaxDynamicSharedMemorySize, gsm_out);
    cudaFuncSetAttribute(attn_tc,
                         cudaFuncAttributeMaxDynamicSharedMemorySize, ATTN_SMEM_BYTES);

    // Launch order keeps attn_tc in the ncu capture slot (4th launch).
    cvt_tf32_kernel<<<256, 256>>>(w_qkv, wqp, DIM*QKVN);
    ln_mod_kernel<<<TOK/8, 256>>>(x, shift, scale, norm_w, norm_b);
    gemm_tc<128,128,4,2><<<dim3(QKVN/128, TOK/128), 256, gsm_qkv>>>(
        hp, wqp, nullptr, qkvp, TOK, QKVN, DIM);
    attn_tc<<<dim3(NN/QROWS, BB*HEADS), 256, ATTN_SMEM_BYTES>>>(qkvp, attnp);
    cvt_tf32_kernel<<<128, 256>>>(w_out, wop, INNER*DIM);
    gemm_tc<64,64,2,4><<<dim3(DIM/64, TOK/64), 256, gsm_out>>>(
        attnp, wop, b_out, out, TOK, DIM, INNER);
}

// round 13
// speedup vs baseline: 1.6368x; 1.6368x over previous
#include <cuda_runtime.h>
#include <cuda_fp16.h>
#include <math.h>
#include <stdint.h>

#define BB 8
#define NN 1024
#define DIM 192
#define HEADS 16
#define DHEAD 64
#define INNER 1024
#define TOK (BB*NN)       // 8192
#define QKVN (3*INNER)    // 3072

// Scratch (allocation-free rule: __device__ globals)
__device__ float  g_h[TOK*DIM];
__device__ __half g_qkvh[(size_t)TOK*QKVN];    // fp16 qkv (48MB)
__device__ float  g_attn[(size_t)TOK*INNER];
__device__ float  g_wqkv[DIM*QKVN];
__device__ float  g_wout[INNER*DIM];

#define QSCALE 0.18033688f   // 0.125 * log2(e), folded into Q weight columns

__device__ __forceinline__ uint32_t f2tf(float x){
    uint32_t u; asm("cvt.rna.tf32.f32 %0, %1;" : "=r"(u) : "f"(x)); return u;
}
__device__ __forceinline__ float ex2(float x){
    float y; asm("ex2.approx.f32 %0, %1;" : "=f"(y) : "f"(x)); return y;
}
// pack two fp32 -> half2 (lo = first arg)
__device__ __forceinline__ uint32_t f2h2(float lo, float hi){
    uint32_t r; asm("cvt.rn.f16x2.f32 %0, %1, %2;" : "=r"(r) : "f"(hi), "f"(lo)); return r;
}

// tf32 m16n8k8 (GEMMs). c0=[g][2t], c1=[g][2t+1], c2=[g+8][2t], c3=[g+8][2t+1]
__device__ __forceinline__ void mma_tf32(float* c, uint32_t a0, uint32_t a1, uint32_t a2, uint32_t a3,
                                         uint32_t b0, uint32_t b1){
    asm volatile("mma.sync.aligned.m16n8k8.row.col.f32.tf32.tf32.f32 "
        "{%0,%1,%2,%3}, {%4,%5,%6,%7}, {%8,%9}, {%0,%1,%2,%3};"
        : "+f"(c[0]), "+f"(c[1]), "+f"(c[2]), "+f"(c[3])
        : "r"(a0), "r"(a1), "r"(a2), "r"(a3), "r"(b0), "r"(b1));
}
// fp16 m16n8k16 with fp32 accum (attention)
__device__ __forceinline__ void mma_f16(float* c, const uint32_t* a, uint32_t b0, uint32_t b1){
    asm volatile("mma.sync.aligned.m16n8k16.row.col.f32.f16.f16.f32 "
        "{%0,%1,%2,%3}, {%4,%5,%6,%7}, {%8,%9}, {%0,%1,%2,%3};"
        : "+f"(c[0]), "+f"(c[1]), "+f"(c[2]), "+f"(c[3])
        : "r"(a[0]), "r"(a[1]), "r"(a[2]), "r"(a[3]), "r"(b0), "r"(b1));
}

__device__ __forceinline__ void ldsm4(uint32_t* r, uint32_t saddr){
    asm volatile("ldmatrix.sync.aligned.m8n8.x4.shared.b16 {%0,%1,%2,%3}, [%4];"
        : "=r"(r[0]), "=r"(r[1]), "=r"(r[2]), "=r"(r[3]) : "r"(saddr));
}
__device__ __forceinline__ void ldsm4t(uint32_t* r, uint32_t saddr){
    asm volatile("ldmatrix.sync.aligned.m8n8.x4.trans.shared.b16 {%0,%1,%2,%3}, [%4];"
        : "=r"(r[0]), "=r"(r[1]), "=r"(r[2]), "=r"(r[3]) : "r"(saddr));
}

__device__ __forceinline__ void cpa16(uint32_t dst, const void* src){
    asm volatile("cp.async.cg.shared.global [%0], [%1], 16;" :: "r"(dst), "l"(src));
}
__device__ __forceinline__ void cp_commit(){ asm volatile("cp.async.commit_group;"); }
template<int N> __device__ __forceinline__ void cp_wait(){
    asm volatile("cp.async.wait_group %0;" :: "n"(N));
}

// ---------------------------------------------------------------------------
// QKV weights: tf32-round, and fold QSCALE into the Q columns (col < INNER)
// ---------------------------------------------------------------------------
__global__ __launch_bounds__(256)
void cvt_wqkv_kernel(const float* __restrict__ src, float* __restrict__ dst, int n){
    for (int i = blockIdx.x*256 + threadIdx.x; i < n; i += gridDim.x*256){
        int col = i % QKVN;
        float v = src[i];
        if (col < INNER) v *= QSCALE;
        dst[i] = __uint_as_float(f2tf(v));
    }
}
__global__ __launch_bounds__(256)
void cvt_tf32_kernel(const float* __restrict__ src, float* __restrict__ dst, int n){
    for (int i = blockIdx.x*256 + threadIdx.x; i < n; i += gridDim.x*256)
        dst[i] = __uint_as_float(f2tf(src[i]));
}

// ---------------------------------------------------------------------------
// LayerNorm + adaLN modulation: one warp per token; output tf32-rounded
// ---------------------------------------------------------------------------
__global__ __launch_bounds__(256)
void ln_mod_kernel(const float* __restrict__ x,
                   const float* __restrict__ shift,
                   const float* __restrict__ scale,
                   const float* __restrict__ w,
                   const float* __restrict__ bpar) {
    int warp = threadIdx.x >> 5;
    int lane = threadIdx.x & 31;
    int t = blockIdx.x * 8 + warp;
    const float* xr = x + (size_t)t * DIM;
    float v[6];
    float s = 0.f;
#pragma unroll
    for (int q = 0; q < 6; q++) { v[q] = xr[lane + q*32]; s += v[q]; }
#pragma unroll
    for (int o = 16; o; o >>= 1) s += __shfl_xor_sync(0xffffffffu, s, o);
    float mu = s * (1.f/DIM);
    float vs = 0.f;
#pragma unroll
    for (int q = 0; q < 6; q++) { float d = v[q]-mu; vs += d*d; }
#pragma unroll
    for (int o = 16; o; o >>= 1) vs += __shfl_xor_sync(0xffffffffu, vs, o);
    float rstd = rsqrtf(vs*(1.f/DIM) + 1e-5f);
    int bi = t >> 10;
#pragma unroll
    for (int q = 0; q < 6; q++) {
        int d = lane + q*32;
        float hn = (v[q]-mu)*rstd*w[d] + bpar[d];
        hn = hn * (1.f + scale[bi*DIM + d]) + shift[bi*DIM + d];
        g_h[(size_t)t*DIM + d] = __uint_as_float(f2tf(hn));
    }
}

// ---------------------------------------------------------------------------
// tf32 TC GEMM (mma.sync). Ch!=nullptr => write fp16 output (QKV path, no bias).
// ---------------------------------------------------------------------------
#define GA_STR 36

template<int BM, int BN, int WR, int WC>
__global__ __launch_bounds__(256, 2)
void gemm_tc(const float* __restrict__ A, const float* __restrict__ Bm,
             const float* __restrict__ bias, float* __restrict__ C,
             __half* __restrict__ Ch, int M, int Nn, int K){
    constexpr int NFR   = (BN/WC)/8;
    constexpr int AIT   = BM*8/256;
    constexpr int BIT   = BN*8/256;
    constexpr int BQ    = BN/4;
    constexpr int B_STR = BN + 8;
    constexpr int ABUF  = BM*GA_STR;
    constexpr int BBUF  = 32*B_STR;
    extern __shared__ uint32_t smg[];
    uint32_t* As = smg;
    uint32_t* Bs = smg + 2*ABUF;
    int m0 = blockIdx.y*BM, n0 = blockIdx.x*BN;
    int tid = threadIdx.x;
    int w = tid>>5, lane = tid&31;
    int g = lane>>2, t = lane&3;
    int wm = w / WC, wn = w % WC;
    uint32_t as_sh = (uint32_t)__cvta_generic_to_shared(As);
    uint32_t bs_sh = (uint32_t)__cvta_generic_to_shared(Bs);
    int a_sub = ((lane>>3)&1)*8 + (lane&7);
    int a_kh  = (lane>>4)*4;

    float acc[2][NFR][4] = {};

    auto issue = [&](int kt, int buf){
#pragma unroll
        for (int i = 0; i < AIT; i++){
            int fid = tid + i*256; int r = fid>>3, cq = fid&7;
            cpa16(as_sh + (uint32_t)(buf*ABUF + r*GA_STR + cq*4)*4,
                  &A[(size_t)(m0+r)*K + kt + cq*4]);
        }
#pragma unroll
        for (int i = 0; i < BIT; i++){
            int fid = tid + i*256; int r = fid/BQ, cq = fid%BQ;
            cpa16(bs_sh + (uint32_t)(buf*BBUF + r*B_STR + cq*4)*4,
                  &Bm[(size_t)(kt+r)*Nn + n0 + cq*4]);
        }
        cp_commit();
    };

    issue(0, 0);
    int nt = K/32;
    for (int it = 0; it < nt; it++){
        int buf = it & 1;
        cp_wait<0>();
        __syncthreads();
        if (it + 1 < nt) issue((it+1)*32, buf^1);
#pragma unroll
        for (int ks = 0; ks < 4; ks++){
            int k0 = ks*8;
            uint32_t af[2][4];
#pragma unroll
            for (int mf = 0; mf < 2; mf++){
                int row = wm*32 + mf*16 + a_sub;
                ldsm4(af[mf], as_sh + (uint32_t)(buf*ABUF + row*GA_STR + k0 + a_kh)*4);
            }
#pragma unroll
            for (int nf = 0; nf < NFR; nf++){
                int col = wn*(BN/WC) + nf*8 + g;
                uint32_t b0 = Bs[buf*BBUF + (k0+t)*B_STR + col];
                uint32_t b1 = Bs[buf*BBUF + (k0+4+t)*B_STR + col];
                mma_tf32(acc[0][nf], af[0][0],af[0][1],af[0][2],af[0][3], b0,b1);
                mma_tf32(acc[1][nf], af[1][0],af[1][1],af[1][2],af[1][3], b0,b1);
            }
        }
        __syncthreads();
    }
#pragma unroll
    for (int mf = 0; mf < 2; mf++){
#pragma unroll
        for (int nf = 0; nf < NFR; nf++){
            int row = m0 + wm*32 + mf*16 + g;
            int col = n0 + wn*(BN/WC) + nf*8 + t*2;
            if (Ch){   // fp16 output (QKV)
                *(uint32_t*)&Ch[(size_t)row*Nn + col] =
                    f2h2(acc[mf][nf][0], acc[mf][nf][1]);
                *(uint32_t*)&Ch[(size_t)(row+8)*Nn + col] =
                    f2h2(acc[mf][nf][2], acc[mf][nf][3]);
            } else {
                float bx = bias ? bias[col] : 0.f;
                float by = bias ? bias[col+1] : 0.f;
                *(float2*)&C[(size_t)row*Nn + col] =
                    make_float2(acc[mf][nf][0]+bx, acc[mf][nf][1]+by);
                *(float2*)&C[(size_t)(row+8)*Nn + col] =
                    make_float2(acc[mf][nf][2]+bx, acc[mf][nf][3]+by);
            }
        }
    }
}

// ---------------------------------------------------------------------------
// Flash attention, fp16 m16n8k16 (fp32 accum). 256 thr, 128 q-rows/CTA,
// warp owns 16 rows. Q frags in regs; P stays in registers (C->A frag match);
// V via ldmatrix.trans. K/V cp.async double-buffered. Base-2 softmax
// (scale folded into Q weights upstream).
// ---------------------------------------------------------------------------
#define KH_STR 72                 // halves per smem row
#define ROWB   144                // bytes per smem row
#define KVBUF  (64*ROWB)          // 9216 B per K or V buffer
#define ATTN_SMEM_BYTES (4*KVBUF) // 36864

__global__ __launch_bounds__(256, 2)
void attn_f16(const __half* __restrict__ qh, float* __restrict__ out){
    extern __shared__ uint32_t sm[];
    uint32_t ks_sh = (uint32_t)__cvta_generic_to_shared(sm);
    uint32_t vs_sh = ks_sh + 2*KVBUF;

    int qt = blockIdx.x, bh = blockIdx.y;  // 128-row q tiles
    int b = bh>>4, h = bh&15;
    int tid = threadIdx.x, w = tid>>5, lane = tid&31;
    int g = lane>>2, t = lane&3;
    int l8 = lane&7, q8 = lane>>3;
    const __half* base = qh + (size_t)b*NN*QKVN + h*DHEAD;

    // lane addressing
    // A-frags (Q): rows w*16.., matrices (rows0-7,klo)(rows8-15,klo)(rows0-7,khi)(rows8-15,khi)
    int arow = w*16 + (q8&1)*8 + l8;
    uint32_t a_off = (uint32_t)arow*ROWB + (q8>>1)*16;
    // B-frags for S (K, non-trans): key = np*16 + ((q8>>1)&1)*8 + l8 ; d-byte = (q8&1)*16
    uint32_t sk_off = (uint32_t)((((q8>>1)&1)*8 + l8))*ROWB + (q8&1)*16;
    // B-frags for PV (V, trans): key = kc*16 + (q8&1)*8 + l8 ; d-byte = (q8>>1)*16
    uint32_t vv_off = (uint32_t)(((q8&1)*8 + l8))*ROWB + (q8>>1)*16;

    // ---- Stage Q (fp16) into K region, pull frags to registers ----
#pragma unroll
    for (int i = 0; i < 4; i++){
        int id = tid + i*256;
        int r = id>>3, c8 = id&7;
        cpa16(ks_sh + (uint32_t)r*ROWB + c8*16,
              &base[(size_t)(qt*128+r)*QKVN + c8*8]);
    }
    cp_commit(); cp_wait<0>();
    __syncthreads();
    uint32_t qf[4][4];
#pragma unroll
    for (int kc = 0; kc < 4; kc++)
        ldsm4(qf[kc], ks_sh + a_off + kc*32);
    __syncthreads();   // Ks free for K tiles

    auto issue = [&](int kt, int buf){
#pragma unroll
        for (int i = 0; i < 2; i++){
            int id = tid + i*256;
            int r = id>>3, c8 = id&7;
            const __half* kr = &base[(size_t)(kt*64+r)*QKVN + INNER + c8*8];
            cpa16(ks_sh + (uint32_t)(buf*KVBUF) + (uint32_t)r*ROWB + c8*16, kr);
            cpa16(vs_sh + (uint32_t)(buf*KVBUF) + (uint32_t)r*ROWB + c8*16, kr + INNER);
        }
        cp_commit();
    };

    float o[8][4] = {};
    float mi0 = -INFINITY, mi1 = -INFINITY, li0 = 0.f, li1 = 0.f;

    issue(0, 0);
    for (int kt = 0; kt < 16; kt++){
        int buf = kt & 1;
        cp_wait<0>();
        __syncthreads();
        if (kt + 1 < 16) issue(kt+1, buf^1);

        // ---- S = Q @ K^T (scores in log2 domain; scale pre-folded) ----
        float s[8][4] = {};
        uint32_t kbase = ks_sh + (uint32_t)(buf*KVBUF) + sk_off;
#pragma unroll
        for (int kc = 0; kc < 4; kc++){
#pragma unroll
            for (int np = 0; np < 4; np++){
                uint32_t kb[4];
                ldsm4(kb, kbase + (uint32_t)(np*16)*ROWB + kc*32);
                mma_f16(s[2*np],   qf[kc], kb[0], kb[1]);
                mma_f16(s[2*np+1], qf[kc], kb[2], kb[3]);
            }
        }

        // ---- Online softmax, base 2 (quad reduce over xor 1,2) ----
        float mx0 = -INFINITY, mx1 = -INFINITY;
#pragma unroll
        for (int nf = 0; nf < 8; nf++){
            mx0 = fmaxf(mx0, fmaxf(s[nf][0], s[nf][1]));
            mx1 = fmaxf(mx1, fmaxf(s[nf][2], s[nf][3]));
        }
        mx0 = fmaxf(mx0, __shfl_xor_sync(0xffffffffu, mx0, 1));
        mx0 = fmaxf(mx0, __shfl_xor_sync(0xffffffffu, mx0, 2));
        mx1 = fmaxf(mx1, __shfl_xor_sync(0xffffffffu, mx1, 1));
        mx1 = fmaxf(mx1, __shfl_xor_sync(0xffffffffu, mx1, 2));
        float mn0 = fmaxf(mi0, mx0), mn1 = fmaxf(mi1, mx1);
        float sc0 = ex2(mi0 - mn0), sc1 = ex2(mi1 - mn1);
        mi0 = mn0; mi1 = mn1;

        float sum0 = 0.f, sum1 = 0.f;
#pragma unroll
        for (int nf = 0; nf < 8; nf++){
            s[nf][0] = ex2(s[nf][0] - mn0); s[nf][1] = ex2(s[nf][1] - mn0);
            s[nf][2] = ex2(s[nf][2] - mn1); s[nf][3] = ex2(s[nf][3] - mn1);
            sum0 += s[nf][0] + s[nf][1];
            sum1 += s[nf][2] + s[nf][3];
        }
        sum0 += __shfl_xor_sync(0xffffffffu, sum0, 1);
        sum0 += __shfl_xor_sync(0xffffffffu, sum0, 2);
        sum1 += __shfl_xor_sync(0xffffffffu, sum1, 1);
        sum1 += __shfl_xor_sync(0xffffffffu, sum1, 2);
        li0 = li0*sc0 + sum0;
        li1 = li1*sc1 + sum1;
#pragma unroll
        for (int nf = 0; nf < 8; nf++){
            o[nf][0] *= sc0; o[nf][1] *= sc0;
            o[nf][2] *= sc1; o[nf][3] *= sc1;
        }

        // ---- O += P @ V : P frags packed straight from C-frags ----
        uint32_t vbase = vs_sh + (uint32_t)(buf*KVBUF) + vv_off;
#pragma unroll
        for (int kc = 0; kc < 4; kc++){
            uint32_t pa[4];
            pa[0] = f2h2(s[2*kc][0],   s[2*kc][1]);
            pa[1] = f2h2(s[2*kc][2],   s[2*kc][3]);
            pa[2] = f2h2(s[2*kc+1][0], s[2*kc+1][1]);
            pa[3] = f2h2(s[2*kc+1][2], s[2*kc+1][3]);
#pragma unroll
            for (int dp = 0; dp < 4; dp++){
                uint32_t vb[4];
                ldsm4t(vb, vbase + (uint32_t)(kc*16)*ROWB + dp*32);
                mma_f16(o[2*dp],   pa, vb[0], vb[1]);
                mma_f16(o[2*dp+1], pa, vb[2], vb[3]);
            }
        }
    }

    // Epilogue: tf32-round for the out-projection GEMM
    float inv0 = 1.f/li0, inv1 = 1.f/li1;
    int row = qt*128 + w*16 + g;
#pragma unroll
    for (int nf = 0; nf < 8; nf++){
        int col = h*DHEAD + nf*8 + t*2;
        *(uint2*)&out[((size_t)(b*NN+row))*INNER + col]   =
            make_uint2(f2tf(o[nf][0]*inv0), f2tf(o[nf][1]*inv0));
        *(uint2*)&out[((size_t)(b*NN+row+8))*INNER + col] =
            make_uint2(f2tf(o[nf][2]*inv1), f2tf(o[nf][3]*inv1));
    }
}

// ---------------------------------------------------------------------------
extern "C" void kernel_launch(void* const* d_in, const int* in_sizes, int n_in,
                              void* d_out, int out_size) {
    const float* x      = (const float*)d_in[0];
    const float* shift  = (const float*)d_in[1];
    const float* scale  = (const float*)d_in[2];
    const float* norm_w = (const float*)d_in[3];
    const float* norm_b = (const float*)d_in[4];
    const float* w_qkv  = (const float*)d_in[5];
    const float* w_out  = (const float*)d_in[6];
    const float* b_out  = (const float*)d_in[7];
    float* out = (float*)d_out;

    float *hp, *attnp, *wqp, *wop;
    __half* qhp;
    cudaGetSymbolAddress((void**)&hp,    g_h);
    cudaGetSymbolAddress((void**)&qhp,   g_qkvh);
    cudaGetSymbolAddress((void**)&attnp, g_attn);
    cudaGetSymbolAddress((void**)&wqp,   g_wqkv);
    cudaGetSymbolAddress((void**)&wop,   g_wout);

    const int gsm_qkv = (2*128*GA_STR + 2*32*(128+8))*4;   // 71680
    const int gsm_out = (2*64*GA_STR  + 2*32*(64+8))*4;    // 36864
    cudaFuncSetAttribute((gemm_tc<128,128,4,2>),
                         cudaFuncAttributeMaxDynamicSharedMemorySize, gsm_qkv);
    cudaFuncSetAttribute((gemm_tc<64,64,2,4>),
                         cudaFuncAttributeMaxDynamicSharedMemorySize, gsm_out);
    cudaFuncSetAttribute(attn_f16,
                         cudaFuncAttributeMaxDynamicSharedMemorySize, ATTN_SMEM_BYTES);

    // Launch order keeps attention in the ncu capture slot (4th launch).
    cvt_wqkv_kernel<<<256, 256>>>(w_qkv, wqp, DIM*QKVN);
    ln_mod_kernel<<<TOK/8, 256>>>(x, shift, scale, norm_w, norm_b);
    gemm_tc<128,128,4,2><<<dim3(QKVN/128, TOK/128), 256, gsm_qkv>>>(
        hp, wqp, nullptr, nullptr, qhp, TOK, QKVN, DIM);
    attn_f16<<<dim3(8, BB*HEADS), 256, ATTN_SMEM_BYTES>>>(qhp, attnp);
    cvt_tf32_kernel<<<128, 256>>>(w_out, wop, INNER*DIM);
    gemm_tc<64,64,2,4><<<dim3(DIM/64, TOK/64), 256, gsm_out>>>(
        attnp, wop, b_out, out, nullptr, TOK, DIM, INNER);
}

// round 14
// speedup vs baseline: 2.0293x; 1.2398x over previous
#include <cuda_runtime.h>
#include <cuda_fp16.h>
#include <math.h>
#include <stdint.h>

#define BB 8
#define NN 1024
#define DIM 192
#define HEADS 16
#define DHEAD 64
#define INNER 1024
#define TOK (BB*NN)       // 8192
#define QKVN (3*INNER)    // 3072

// Scratch (allocation-free rule: __device__ globals)
__device__ __half g_hh[TOK*DIM];               // fp16 LN output
__device__ __half g_qkvh[(size_t)TOK*QKVN];    // fp16 qkv
__device__ __half g_attnh[(size_t)TOK*INNER];  // fp16 attention output
__device__ __half g_wqkvh[DIM*QKVN];           // fp16 weights (QSCALE folded)
__device__ __half g_wouth[INNER*DIM];

#define QSCALE 0.18033688f   // 0.125 * log2(e), folded into Q weight columns

__device__ __forceinline__ float ex2(float x){
    float y; asm("ex2.approx.f32 %0, %1;" : "=f"(y) : "f"(x)); return y;
}
// pack two fp32 -> half2 (lo = first arg)
__device__ __forceinline__ uint32_t f2h2(float lo, float hi){
    uint32_t r; asm("cvt.rn.f16x2.f32 %0, %1, %2;" : "=r"(r) : "f"(hi), "f"(lo)); return r;
}

// fp16 m16n8k16 with fp32 accum
__device__ __forceinline__ void mma_f16(float* c, const uint32_t* a, uint32_t b0, uint32_t b1){
    asm volatile("mma.sync.aligned.m16n8k16.row.col.f32.f16.f16.f32 "
        "{%0,%1,%2,%3}, {%4,%5,%6,%7}, {%8,%9}, {%0,%1,%2,%3};"
        : "+f"(c[0]), "+f"(c[1]), "+f"(c[2]), "+f"(c[3])
        : "r"(a[0]), "r"(a[1]), "r"(a[2]), "r"(a[3]), "r"(b0), "r"(b1));
}

__device__ __forceinline__ void ldsm4(uint32_t* r, uint32_t saddr){
    asm volatile("ldmatrix.sync.aligned.m8n8.x4.shared.b16 {%0,%1,%2,%3}, [%4];"
        : "=r"(r[0]), "=r"(r[1]), "=r"(r[2]), "=r"(r[3]) : "r"(saddr));
}
__device__ __forceinline__ void ldsm4t(uint32_t* r, uint32_t saddr){
    asm volatile("ldmatrix.sync.aligned.m8n8.x4.trans.shared.b16 {%0,%1,%2,%3}, [%4];"
        : "=r"(r[0]), "=r"(r[1]), "=r"(r[2]), "=r"(r[3]) : "r"(saddr));
}

__device__ __forceinline__ void cpa16(uint32_t dst, const void* src){
    asm volatile("cp.async.cg.shared.global [%0], [%1], 16;" :: "r"(dst), "l"(src));
}
__device__ __forceinline__ void cp_commit(){ asm volatile("cp.async.commit_group;"); }
template<int N> __device__ __forceinline__ void cp_wait(){
    asm volatile("cp.async.wait_group %0;" :: "n"(N));
}

// ---------------------------------------------------------------------------
// Weight conversion fp32 -> fp16 (QKV variant folds QSCALE into Q columns)
// ---------------------------------------------------------------------------
__global__ __launch_bounds__(256)
void cvt_wqkv_h(const float* __restrict__ src, __half* __restrict__ dst, int n){
    for (int i = blockIdx.x*256 + threadIdx.x; i < n; i += gridDim.x*256){
        int col = i % QKVN;
        float v = src[i];
        if (col < INNER) v *= QSCALE;
        dst[i] = __float2half_rn(v);
    }
}
__global__ __launch_bounds__(256)
void cvt_w_h(const float* __restrict__ src, __half* __restrict__ dst, int n){
    for (int i = blockIdx.x*256 + threadIdx.x; i < n; i += gridDim.x*256)
        dst[i] = __float2half_rn(src[i]);
}

// ---------------------------------------------------------------------------
// LayerNorm + adaLN modulation: one warp per token; fp16 output
// ---------------------------------------------------------------------------
__global__ __launch_bounds__(256)
void ln_mod_kernel(const float* __restrict__ x,
                   const float* __restrict__ shift,
                   const float* __restrict__ scale,
                   const float* __restrict__ w,
                   const float* __restrict__ bpar) {
    int warp = threadIdx.x >> 5;
    int lane = threadIdx.x & 31;
    int t = blockIdx.x * 8 + warp;
    const float* xr = x + (size_t)t * DIM;
    float v[6];
    float s = 0.f;
#pragma unroll
    for (int q = 0; q < 6; q++) { v[q] = xr[lane + q*32]; s += v[q]; }
#pragma unroll
    for (int o = 16; o; o >>= 1) s += __shfl_xor_sync(0xffffffffu, s, o);
    float mu = s * (1.f/DIM);
    float vs = 0.f;
#pragma unroll
    for (int q = 0; q < 6; q++) { float d = v[q]-mu; vs += d*d; }
#pragma unroll
    for (int o = 16; o; o >>= 1) vs += __shfl_xor_sync(0xffffffffu, vs, o);
    float rstd = rsqrtf(vs*(1.f/DIM) + 1e-5f);
    int bi = t >> 10;
#pragma unroll
    for (int q = 0; q < 6; q++) {
        int d = lane + q*32;
        float hn = (v[q]-mu)*rstd*w[d] + bpar[d];
        hn = hn * (1.f + scale[bi*DIM + d]) + shift[bi*DIM + d];
        g_hh[(size_t)t*DIM + d] = __float2half_rn(hn);
    }
}

// ---------------------------------------------------------------------------
// fp16 TC GEMM (m16n8k16, fp32 accum). BK=32, 256 thr, 8 warps (BM/32 x WC).
// A [M][K] fp16, B [K][N] fp16 (B-frags via ldmatrix.trans).
// Ch != nullptr -> fp16 output (QKV); else fp32 + bias (out-proj).
// ---------------------------------------------------------------------------
#define AH_ROWB 80               // bytes per A smem row (32 halves + pad)

template<int BM, int BN, int WC>
__global__ __launch_bounds__(256, 2)
void gemm_f16(const __half* __restrict__ A, const __half* __restrict__ Bm,
              const float* __restrict__ bias, float* __restrict__ C,
              __half* __restrict__ Ch, int M, int Nn, int K){
    constexpr int NFR    = (BN/WC)/8;    // 8-col frags per warp
    constexpr int AIT    = BM/64;        // 16B A chunks / 256 thr
    constexpr int BIT    = BN/64;
    constexpr int BQ     = BN/8;         // 16B chunks per B row
    constexpr int B_STRB = (BN+8)*2;     // bytes per B smem row
    constexpr int ABUF   = BM*AH_ROWB;
    constexpr int BBUF   = 32*B_STRB;
    extern __shared__ uint32_t smg[];
    uint32_t a_sh = (uint32_t)__cvta_generic_to_shared(smg);
    uint32_t b_sh = a_sh + 2*ABUF;
    int m0 = blockIdx.y*BM, n0 = blockIdx.x*BN;
    int tid = threadIdx.x;
    int w = tid>>5, lane = tid&31;
    int g = lane>>2, t = lane&3;
    int l8 = lane&7, q8 = lane>>3;
    int wm = w / WC, wn = w % WC;
    uint32_t a_off = (uint32_t)((q8&1)*8 + l8)*AH_ROWB + (q8>>1)*16;
    uint32_t b_off = (uint32_t)((q8&1)*8 + l8)*B_STRB + (q8>>1)*16;

    float acc[2][NFR][4] = {};

    auto issue = [&](int kt, int buf){
#pragma unroll
        for (int i = 0; i < AIT; i++){
            int fid = tid + i*256; int r = fid>>2, c = fid&3;
            cpa16(a_sh + (uint32_t)(buf*ABUF) + (uint32_t)r*AH_ROWB + c*16,
                  &A[(size_t)(m0+r)*K + kt + c*8]);
        }
#pragma unroll
        for (int i = 0; i < BIT; i++){
            int fid = tid + i*256; int r = fid/BQ, c = fid%BQ;
            cpa16(b_sh + (uint32_t)(buf*BBUF) + (uint32_t)r*B_STRB + c*16,
                  &Bm[(size_t)(kt+r)*Nn + n0 + c*8]);
        }
        cp_commit();
    };

    issue(0, 0);
    int nt = K/32;
    for (int it = 0; it < nt; it++){
        int buf = it & 1;
        cp_wait<0>();
        __syncthreads();
        if (it + 1 < nt) issue((it+1)*32, buf^1);
#pragma unroll
        for (int kc = 0; kc < 2; kc++){
            uint32_t af[2][4];
#pragma unroll
            for (int mf = 0; mf < 2; mf++)
                ldsm4(af[mf], a_sh + (uint32_t)(buf*ABUF)
                      + (uint32_t)(wm*32 + mf*16)*AH_ROWB + a_off + kc*32);
#pragma unroll
            for (int np = 0; np < NFR/2; np++){
                uint32_t bb[4];
                ldsm4t(bb, b_sh + (uint32_t)(buf*BBUF)
                       + (uint32_t)(kc*16)*B_STRB + b_off
                       + (uint32_t)(wn*(BN/WC) + np*16)*2);
                mma_f16(acc[0][2*np],   af[0], bb[0], bb[1]);
                mma_f16(acc[0][2*np+1], af[0], bb[2], bb[3]);
                mma_f16(acc[1][2*np],   af[1], bb[0], bb[1]);
                mma_f16(acc[1][2*np+1], af[1], bb[2], bb[3]);
            }
        }
        __syncthreads();
    }
#pragma unroll
    for (int mf = 0; mf < 2; mf++){
#pragma unroll
        for (int nf = 0; nf < NFR; nf++){
            int row = m0 + wm*32 + mf*16 + g;
            int col = n0 + wn*(BN/WC) + nf*8 + t*2;
            if (Ch){
                *(uint32_t*)&Ch[(size_t)row*Nn + col] =
                    f2h2(acc[mf][nf][0], acc[mf][nf][1]);
                *(uint32_t*)&Ch[(size_t)(row+8)*Nn + col] =
                    f2h2(acc[mf][nf][2], acc[mf][nf][3]);
            } else {
                float bx = bias ? bias[col] : 0.f;
                float by = bias ? bias[col+1] : 0.f;
                *(float2*)&C[(size_t)row*Nn + col] =
                    make_float2(acc[mf][nf][0]+bx, acc[mf][nf][1]+by);
                *(float2*)&C[(size_t)(row+8)*Nn + col] =
                    make_float2(acc[mf][nf][2]+bx, acc[mf][nf][3]+by);
            }
        }
    }
}

// ---------------------------------------------------------------------------
// Flash attention, fp16 m16n8k16 (fp32 accum). 256 thr, 128 q-rows/CTA,
// warp owns 16 rows. Q frags in regs; P register-resident; V via ldsm.trans.
// K/V cp.async double-buffered. Base-2 softmax (scale pre-folded into weights).
// fp16 output for the out-projection GEMM.
// ---------------------------------------------------------------------------
#define ROWB   144                // bytes per K/V smem row (64 halves + pad)
#define KVBUF  (64*ROWB)          // 9216 B per buffer
#define ATTN_SMEM_BYTES (4*KVBUF) // 36864

__global__ __launch_bounds__(256, 2)
void attn_f16(const __half* __restrict__ qh, __half* __restrict__ outh){
    extern __shared__ uint32_t sm[];
    uint32_t ks_sh = (uint32_t)__cvta_generic_to_shared(sm);
    uint32_t vs_sh = ks_sh + 2*KVBUF;

    int qt = blockIdx.x, bh = blockIdx.y;  // 128-row q tiles
    int b = bh>>4, h = bh&15;
    int tid = threadIdx.x, w = tid>>5, lane = tid&31;
    int g = lane>>2, t = lane&3;
    int l8 = lane&7, q8 = lane>>3;
    const __half* base = qh + (size_t)b*NN*QKVN + h*DHEAD;

    int arow = w*16 + (q8&1)*8 + l8;
    uint32_t a_off = (uint32_t)arow*ROWB + (q8>>1)*16;
    uint32_t sk_off = (uint32_t)((((q8>>1)&1)*8 + l8))*ROWB + (q8&1)*16;
    uint32_t vv_off = (uint32_t)(((q8&1)*8 + l8))*ROWB + (q8>>1)*16;

    // ---- Stage Q (fp16) into K region, pull frags to registers ----
#pragma unroll
    for (int i = 0; i < 4; i++){
        int id = tid + i*256;
        int r = id>>3, c8 = id&7;
        cpa16(ks_sh + (uint32_t)r*ROWB + c8*16,
              &base[(size_t)(qt*128+r)*QKVN + c8*8]);
    }
    cp_commit(); cp_wait<0>();
    __syncthreads();
    uint32_t qf[4][4];
#pragma unroll
    for (int kc = 0; kc < 4; kc++)
        ldsm4(qf[kc], ks_sh + a_off + kc*32);
    __syncthreads();   // Ks free for K tiles

    auto issue = [&](int kt, int buf){
#pragma unroll
        for (int i = 0; i < 2; i++){
            int id = tid + i*256;
            int r = id>>3, c8 = id&7;
            const __half* kr = &base[(size_t)(kt*64+r)*QKVN + INNER + c8*8];
            cpa16(ks_sh + (uint32_t)(buf*KVBUF) + (uint32_t)r*ROWB + c8*16, kr);
            cpa16(vs_sh + (uint32_t)(buf*KVBUF) + (uint32_t)r*ROWB + c8*16, kr + INNER);
        }
        cp_commit();
    };

    float o[8][4] = {};
    float mi0 = -INFINITY, mi1 = -INFINITY, li0 = 0.f, li1 = 0.f;

    issue(0, 0);
    for (int kt = 0; kt < 16; kt++){
        int buf = kt & 1;
        cp_wait<0>();
        __syncthreads();
        if (kt + 1 < 16) issue(kt+1, buf^1);

        // ---- S = Q @ K^T (log2 domain; scale pre-folded) ----
        float s[8][4] = {};
        uint32_t kbase = ks_sh + (uint32_t)(buf*KVBUF) + sk_off;
#pragma unroll
        for (int kc = 0; kc < 4; kc++){
#pragma unroll
            for (int np = 0; np < 4; np++){
                uint32_t kb[4];
                ldsm4(kb, kbase + (uint32_t)(np*16)*ROWB + kc*32);
                mma_f16(s[2*np],   qf[kc], kb[0], kb[1]);
                mma_f16(s[2*np+1], qf[kc], kb[2], kb[3]);
            }
        }

        // ---- Online softmax, base 2 (quad reduce over xor 1,2) ----
        float mx0 = -INFINITY, mx1 = -INFINITY;
#pragma unroll
        for (int nf = 0; nf < 8; nf++){
            mx0 = fmaxf(mx0, fmaxf(s[nf][0], s[nf][1]));
            mx1 = fmaxf(mx1, fmaxf(s[nf][2], s[nf][3]));
        }
        mx0 = fmaxf(mx0, __shfl_xor_sync(0xffffffffu, mx0, 1));
        mx0 = fmaxf(mx0, __shfl_xor_sync(0xffffffffu, mx0, 2));
        mx1 = fmaxf(mx1, __shfl_xor_sync(0xffffffffu, mx1, 1));
        mx1 = fmaxf(mx1, __shfl_xor_sync(0xffffffffu, mx1, 2));
        float mn0 = fmaxf(mi0, mx0), mn1 = fmaxf(mi1, mx1);
        float sc0 = ex2(mi0 - mn0), sc1 = ex2(mi1 - mn1);
        mi0 = mn0; mi1 = mn1;

        float sum0 = 0.f, sum1 = 0.f;
#pragma unroll
        for (int nf = 0; nf < 8; nf++){
            s[nf][0] = ex2(s[nf][0] - mn0); s[nf][1] = ex2(s[nf][1] - mn0);
            s[nf][2] = ex2(s[nf][2] - mn1); s[nf][3] = ex2(s[nf][3] - mn1);
            sum0 += s[nf][0] + s[nf][1];
            sum1 += s[nf][2] + s[nf][3];
        }
        sum0 += __shfl_xor_sync(0xffffffffu, sum0, 1);
        sum0 += __shfl_xor_sync(0xffffffffu, sum0, 2);
        sum1 += __shfl_xor_sync(0xffffffffu, sum1, 1);
        sum1 += __shfl_xor_sync(0xffffffffu, sum1, 2);
        li0 = li0*sc0 + sum0;
        li1 = li1*sc1 + sum1;
#pragma unroll
        for (int nf = 0; nf < 8; nf++){
            o[nf][0] *= sc0; o[nf][1] *= sc0;
            o[nf][2] *= sc1; o[nf][3] *= sc1;
        }

        // ---- O += P @ V : P frags packed straight from C-frags ----
        uint32_t vbase = vs_sh + (uint32_t)(buf*KVBUF) + vv_off;
#pragma unroll
        for (int kc = 0; kc < 4; kc++){
            uint32_t pa[4];
            pa[0] = f2h2(s[2*kc][0],   s[2*kc][1]);
            pa[1] = f2h2(s[2*kc][2],   s[2*kc][3]);
            pa[2] = f2h2(s[2*kc+1][0], s[2*kc+1][1]);
            pa[3] = f2h2(s[2*kc+1][2], s[2*kc+1][3]);
#pragma unroll
            for (int dp = 0; dp < 4; dp++){
                uint32_t vb[4];
                ldsm4t(vb, vbase + (uint32_t)(kc*16)*ROWB + dp*32);
                mma_f16(o[2*dp],   pa, vb[0], vb[1]);
                mma_f16(o[2*dp+1], pa, vb[2], vb[3]);
            }
        }
    }

    // Epilogue: fp16 output for the out-projection GEMM
    float inv0 = 1.f/li0, inv1 = 1.f/li1;
    int row = qt*128 + w*16 + g;
#pragma unroll
    for (int nf = 0; nf < 8; nf++){
        int col = h*DHEAD + nf*8 + t*2;
        *(uint32_t*)&outh[((size_t)(b*NN+row))*INNER + col]   =
            f2h2(o[nf][0]*inv0, o[nf][1]*inv0);
        *(uint32_t*)&outh[((size_t)(b*NN+row+8))*INNER + col] =
            f2h2(o[nf][2]*inv1, o[nf][3]*inv1);
    }
}

// ---------------------------------------------------------------------------
extern "C" void kernel_launch(void* const* d_in, const int* in_sizes, int n_in,
                              void* d_out, int out_size) {
    const float* x      = (const float*)d_in[0];
    const float* shift  = (const float*)d_in[1];
    const float* scale  = (const float*)d_in[2];
    const float* norm_w = (const float*)d_in[3];
    const float* norm_b = (const float*)d_in[4];
    const float* w_qkv  = (const float*)d_in[5];
    const float* w_out  = (const float*)d_in[6];
    const float* b_out  = (const float*)d_in[7];
    float* out = (float*)d_out;

    __half *hp, *qhp, *attnp, *wqp, *wop;
    cudaGetSymbolAddress((void**)&hp,    g_hh);
    cudaGetSymbolAddress((void**)&qhp,   g_qkvh);
    cudaGetSymbolAddress((void**)&attnp, g_attnh);
    cudaGetSymbolAddress((void**)&wqp,   g_wqkvh);
    cudaGetSymbolAddress((void**)&wop,   g_wouth);

    // smem: 2*BM*80 + 2*32*(BN+8)*2
    const int gsm_qkv = 2*128*AH_ROWB + 2*32*(128+8)*2;   // 37888
    const int gsm_out = 2*64*AH_ROWB  + 2*32*(64+8)*2;    // 19456
    cudaFuncSetAttribute((gemm_f16<128,128,2>),
                         cudaFuncAttributeMaxDynamicSharedMemorySize, gsm_qkv);
    cudaFuncSetAttribute((gemm_f16<64,64,4>),
                         cudaFuncAttributeMaxDynamicSharedMemorySize, gsm_out);
    cudaFuncSetAttribute(attn_f16,
                         cudaFuncAttributeMaxDynamicSharedMemorySize, ATTN_SMEM_BYTES);

    // Launch order keeps attention in the ncu capture slot (4th launch).
    cvt_wqkv_h<<<256, 256>>>(w_qkv, wqp, DIM*QKVN);
    ln_mod_kernel<<<TOK/8, 256>>>(x, shift, scale, norm_w, norm_b);
    gemm_f16<128,128,2><<<dim3(QKVN/128, TOK/128), 256, gsm_qkv>>>(
        hp, wqp, nullptr, nullptr, qhp, TOK, QKVN, DIM);
    attn_f16<<<dim3(8, BB*HEADS), 256, ATTN_SMEM_BYTES>>>(qhp, attnp);
    cvt_w_h<<<128, 256>>>(w_out, wop, INNER*DIM);
    gemm_f16<64,64,4><<<dim3(DIM/64, TOK/64), 256, gsm_out>>>(
        attnp, wop, b_out, out, nullptr, TOK, DIM, INNER);
}

// round 15
// speedup vs baseline: 2.1254x; 1.0474x over previous
#include <cuda_runtime.h>
#include <cuda_fp16.h>
#include <math.h>
#include <stdint.h>

#define BB 8
#define NN 1024
#define DIM 192
#define HEADS 16
#define DHEAD 64
#define INNER 1024
#define TOK (BB*NN)       // 8192
#define QKVN (3*INNER)    // 3072

// Scratch (allocation-free rule: __device__ globals)
__device__ __half g_hh[TOK*DIM];               // fp16 LN output
__device__ __half g_qkvh[(size_t)TOK*QKVN];    // fp16 qkv
__device__ __half g_attnh[(size_t)TOK*INNER];  // fp16 attention output
__device__ __half g_wqkvh[DIM*QKVN];           // fp16 weights (QSCALE folded)
__device__ __half g_wouth[INNER*DIM];

#define QSCALE 0.18033688f   // 0.125 * log2(e), folded into Q weight columns
#define ONES_H2 0x3C003C00u  // half2(1.0, 1.0)

__device__ __forceinline__ float ex2(float x){
    float y; asm("ex2.approx.f32 %0, %1;" : "=f"(y) : "f"(x)); return y;
}
__device__ __forceinline__ uint32_t ex2h2(uint32_t x){
    uint32_t y; asm("ex2.approx.f16x2 %0, %1;" : "=r"(y) : "r"(x)); return y;
}
// pack two fp32 -> half2 (lo = first arg)
__device__ __forceinline__ uint32_t f2h2(float lo, float hi){
    uint32_t r; asm("cvt.rn.f16x2.f32 %0, %1, %2;" : "=r"(r) : "f"(hi), "f"(lo)); return r;
}

// fp16 m16n8k16 with fp32 accum
__device__ __forceinline__ void mma_f16(float* c, const uint32_t* a, uint32_t b0, uint32_t b1){
    asm volatile("mma.sync.aligned.m16n8k16.row.col.f32.f16.f16.f32 "
        "{%0,%1,%2,%3}, {%4,%5,%6,%7}, {%8,%9}, {%0,%1,%2,%3};"
        : "+f"(c[0]), "+f"(c[1]), "+f"(c[2]), "+f"(c[3])
        : "r"(a[0]), "r"(a[1]), "r"(a[2]), "r"(a[3]), "r"(b0), "r"(b1));
}

__device__ __forceinline__ void ldsm4(uint32_t* r, uint32_t saddr){
    asm volatile("ldmatrix.sync.aligned.m8n8.x4.shared.b16 {%0,%1,%2,%3}, [%4];"
        : "=r"(r[0]), "=r"(r[1]), "=r"(r[2]), "=r"(r[3]) : "r"(saddr));
}
__device__ __forceinline__ void ldsm4t(uint32_t* r, uint32_t saddr){
    asm volatile("ldmatrix.sync.aligned.m8n8.x4.trans.shared.b16 {%0,%1,%2,%3}, [%4];"
        : "=r"(r[0]), "=r"(r[1]), "=r"(r[2]), "=r"(r[3]) : "r"(saddr));
}

__device__ __forceinline__ void cpa16(uint32_t dst, const void* src){
    asm volatile("cp.async.cg.shared.global [%0], [%1], 16;" :: "r"(dst), "l"(src));
}
__device__ __forceinline__ void cp_commit(){ asm volatile("cp.async.commit_group;"); }
template<int N> __device__ __forceinline__ void cp_wait(){
    asm volatile("cp.async.wait_group %0;" :: "n"(N));
}

// ---------------------------------------------------------------------------
// Weight conversion fp32 -> fp16 (QKV variant folds QSCALE into Q columns)
// ---------------------------------------------------------------------------
__global__ __launch_bounds__(256)
void cvt_wqkv_h(const float* __restrict__ src, __half* __restrict__ dst, int n){
    for (int i = blockIdx.x*256 + threadIdx.x; i < n; i += gridDim.x*256){
        int col = i % QKVN;
        float v = src[i];
        if (col < INNER) v *= QSCALE;
        dst[i] = __float2half_rn(v);
    }
}
__global__ __launch_bounds__(256)
void cvt_w_h(const float* __restrict__ src, __half* __restrict__ dst, int n){
    for (int i = blockIdx.x*256 + threadIdx.x; i < n; i += gridDim.x*256)
        dst[i] = __float2half_rn(src[i]);
}

// ---------------------------------------------------------------------------
// LayerNorm + adaLN modulation: one warp per token; fp16 output
// ---------------------------------------------------------------------------
__global__ __launch_bounds__(256)
void ln_mod_kernel(const float* __restrict__ x,
                   const float* __restrict__ shift,
                   const float* __restrict__ scale,
                   const float* __restrict__ w,
                   const float* __restrict__ bpar) {
    int warp = threadIdx.x >> 5;
    int lane = threadIdx.x & 31;
    int t = blockIdx.x * 8 + warp;
    const float* xr = x + (size_t)t * DIM;
    float v[6];
    float s = 0.f;
#pragma unroll
    for (int q = 0; q < 6; q++) { v[q] = xr[lane + q*32]; s += v[q]; }
#pragma unroll
    for (int o = 16; o; o >>= 1) s += __shfl_xor_sync(0xffffffffu, s, o);
    float mu = s * (1.f/DIM);
    float vs = 0.f;
#pragma unroll
    for (int q = 0; q < 6; q++) { float d = v[q]-mu; vs += d*d; }
#pragma unroll
    for (int o = 16; o; o >>= 1) vs += __shfl_xor_sync(0xffffffffu, vs, o);
    float rstd = rsqrtf(vs*(1.f/DIM) + 1e-5f);
    int bi = t >> 10;
#pragma unroll
    for (int q = 0; q < 6; q++) {
        int d = lane + q*32;
        float hn = (v[q]-mu)*rstd*w[d] + bpar[d];
        hn = hn * (1.f + scale[bi*DIM + d]) + shift[bi*DIM + d];
        g_hh[(size_t)t*DIM + d] = __float2half_rn(hn);
    }
}

// ---------------------------------------------------------------------------
// fp16 TC GEMM (m16n8k16, fp32 accum). BK=32, 256 thr, 8 warps.
// A [M][K] fp16, B [K][N] fp16 (B-frags via ldmatrix.trans).
// Ch != nullptr -> fp16 output (QKV); else fp32 + bias (out-proj).
// ---------------------------------------------------------------------------
#define AH_ROWB 80               // bytes per A smem row (32 halves + pad)

template<int BM, int BN, int WC>
__global__ __launch_bounds__(256, 2)
void gemm_f16(const __half* __restrict__ A, const __half* __restrict__ Bm,
              const float* __restrict__ bias, float* __restrict__ C,
              __half* __restrict__ Ch, int M, int Nn, int K){
    constexpr int NFR    = (BN/WC)/8;
    constexpr int AIT    = BM/64;
    constexpr int BIT    = BN/64;
    constexpr int BQ     = BN/8;
    constexpr int B_STRB = (BN+8)*2;
    constexpr int ABUF   = BM*AH_ROWB;
    constexpr int BBUF   = 32*B_STRB;
    extern __shared__ uint32_t smg[];
    uint32_t a_sh = (uint32_t)__cvta_generic_to_shared(smg);
    uint32_t b_sh = a_sh + 2*ABUF;
    int m0 = blockIdx.y*BM, n0 = blockIdx.x*BN;
    int tid = threadIdx.x;
    int w = tid>>5, lane = tid&31;
    int g = lane>>2, t = lane&3;
    int l8 = lane&7, q8 = lane>>3;
    int wm = w / WC, wn = w % WC;
    uint32_t a_off = (uint32_t)((q8&1)*8 + l8)*AH_ROWB + (q8>>1)*16;
    uint32_t b_off = (uint32_t)((q8&1)*8 + l8)*B_STRB + (q8>>1)*16;

    float acc[2][NFR][4] = {};

    auto issue = [&](int kt, int buf){
#pragma unroll
        for (int i = 0; i < AIT; i++){
            int fid = tid + i*256; int r = fid>>2, c = fid&3;
            cpa16(a_sh + (uint32_t)(buf*ABUF) + (uint32_t)r*AH_ROWB + c*16,
                  &A[(size_t)(m0+r)*K + kt + c*8]);
        }
#pragma unroll
        for (int i = 0; i < BIT; i++){
            int fid = tid + i*256; int r = fid/BQ, c = fid%BQ;
            cpa16(b_sh + (uint32_t)(buf*BBUF) + (uint32_t)r*B_STRB + c*16,
                  &Bm[(size_t)(kt+r)*Nn + n0 + c*8]);
        }
        cp_commit();
    };

    issue(0, 0);
    int nt = K/32;
    for (int it = 0; it < nt; it++){
        int buf = it & 1;
        cp_wait<0>();
        __syncthreads();
        if (it + 1 < nt) issue((it+1)*32, buf^1);
#pragma unroll
        for (int kc = 0; kc < 2; kc++){
            uint32_t af[2][4];
#pragma unroll
            for (int mf = 0; mf < 2; mf++)
                ldsm4(af[mf], a_sh + (uint32_t)(buf*ABUF)
                      + (uint32_t)(wm*32 + mf*16)*AH_ROWB + a_off + kc*32);
#pragma unroll
            for (int np = 0; np < NFR/2; np++){
                uint32_t bb[4];
                ldsm4t(bb, b_sh + (uint32_t)(buf*BBUF)
                       + (uint32_t)(kc*16)*B_STRB + b_off
                       + (uint32_t)(wn*(BN/WC) + np*16)*2);
                mma_f16(acc[0][2*np],   af[0], bb[0], bb[1]);
                mma_f16(acc[0][2*np+1], af[0], bb[2], bb[3]);
                mma_f16(acc[1][2*np],   af[1], bb[0], bb[1]);
                mma_f16(acc[1][2*np+1], af[1], bb[2], bb[3]);
            }
        }
        __syncthreads();
    }
#pragma unroll
    for (int mf = 0; mf < 2; mf++){
#pragma unroll
        for (int nf = 0; nf < NFR; nf++){
            int row = m0 + wm*32 + mf*16 + g;
            int col = n0 + wn*(BN/WC) + nf*8 + t*2;
            if (Ch){
                *(uint32_t*)&Ch[(size_t)row*Nn + col] =
                    f2h2(acc[mf][nf][0], acc[mf][nf][1]);
                *(uint32_t*)&Ch[(size_t)(row+8)*Nn + col] =
                    f2h2(acc[mf][nf][2], acc[mf][nf][3]);
            } else {
                float bx = bias ? bias[col] : 0.f;
                float by = bias ? bias[col+1] : 0.f;
                *(float2*)&C[(size_t)row*Nn + col] =
                    make_float2(acc[mf][nf][0]+bx, acc[mf][nf][1]+by);
                *(float2*)&C[(size_t)(row+8)*Nn + col] =
                    make_float2(acc[mf][nf][2]+bx, acc[mf][nf][3]+by);
            }
        }
    }
}

// ---------------------------------------------------------------------------
// Flash attention, fp16 m16n8k16 (fp32 accum). 256 thr, 128 q-rows/CTA.
// Q frags in regs; P register-resident via f16x2 ex2 (exp fused into A-frag
// packing); row-sum li computed by MMA against a constant all-ones B-frag.
// V via ldsm.trans. K/V cp.async double-buffered. Base-2 softmax.
// ---------------------------------------------------------------------------
#define ROWB   144                // bytes per K/V smem row (64 halves + pad)
#define KVBUF  (64*ROWB)          // 9216 B per buffer
#define ATTN_SMEM_BYTES (4*KVBUF) // 36864

__global__ __launch_bounds__(256, 2)
void attn_f16(const __half* __restrict__ qh, __half* __restrict__ outh){
    extern __shared__ uint32_t sm[];
    uint32_t ks_sh = (uint32_t)__cvta_generic_to_shared(sm);
    uint32_t vs_sh = ks_sh + 2*KVBUF;

    int qt = blockIdx.x, bh = blockIdx.y;  // 128-row q tiles
    int b = bh>>4, h = bh&15;
    int tid = threadIdx.x, w = tid>>5, lane = tid&31;
    int g = lane>>2, t = lane&3;
    int l8 = lane&7, q8 = lane>>3;
    const __half* base = qh + (size_t)b*NN*QKVN + h*DHEAD;

    int arow = w*16 + (q8&1)*8 + l8;
    uint32_t a_off = (uint32_t)arow*ROWB + (q8>>1)*16;
    uint32_t sk_off = (uint32_t)((((q8>>1)&1)*8 + l8))*ROWB + (q8&1)*16;
    uint32_t vv_off = (uint32_t)(((q8&1)*8 + l8))*ROWB + (q8>>1)*16;

    // ---- Stage Q (fp16) into K region, pull frags to registers ----
#pragma unroll
    for (int i = 0; i < 4; i++){
        int id = tid + i*256;
        int r = id>>3, c8 = id&7;
        cpa16(ks_sh + (uint32_t)r*ROWB + c8*16,
              &base[(size_t)(qt*128+r)*QKVN + c8*8]);
    }
    cp_commit(); cp_wait<0>();
    __syncthreads();
    uint32_t qf[4][4];
#pragma unroll
    for (int kc = 0; kc < 4; kc++)
        ldsm4(qf[kc], ks_sh + a_off + kc*32);
    __syncthreads();   // Ks free for K tiles

    auto issue = [&](int kt, int buf){
#pragma unroll
        for (int i = 0; i < 2; i++){
            int id = tid + i*256;
            int r = id>>3, c8 = id&7;
            const __half* kr = &base[(size_t)(kt*64+r)*QKVN + INNER + c8*8];
            cpa16(ks_sh + (uint32_t)(buf*KVBUF) + (uint32_t)r*ROWB + c8*16, kr);
            cpa16(vs_sh + (uint32_t)(buf*KVBUF) + (uint32_t)r*ROWB + c8*16, kr + INNER);
        }
        cp_commit();
    };

    float o[8][4] = {};
    float oS[4] = {};                     // ones-column accumulator (li sums)
    float mi0 = -INFINITY, mi1 = -INFINITY;

    issue(0, 0);
    for (int kt = 0; kt < 16; kt++){
        int buf = kt & 1;
        cp_wait<0>();
        __syncthreads();
        if (kt + 1 < 16) issue(kt+1, buf^1);

        // ---- S = Q @ K^T (log2 domain; scale pre-folded) ----
        float s[8][4] = {};
        uint32_t kbase = ks_sh + (uint32_t)(buf*KVBUF) + sk_off;
#pragma unroll
        for (int kc = 0; kc < 4; kc++){
#pragma unroll
            for (int np = 0; np < 4; np++){
                uint32_t kb[4];
                ldsm4(kb, kbase + (uint32_t)(np*16)*ROWB + kc*32);
                mma_f16(s[2*np],   qf[kc], kb[0], kb[1]);
                mma_f16(s[2*np+1], qf[kc], kb[2], kb[3]);
            }
        }

        // ---- Online softmax: max reduce + o rescale only ----
        float mx0 = -INFINITY, mx1 = -INFINITY;
#pragma unroll
        for (int nf = 0; nf < 8; nf++){
            mx0 = fmaxf(mx0, fmaxf(s[nf][0], s[nf][1]));
            mx1 = fmaxf(mx1, fmaxf(s[nf][2], s[nf][3]));
        }
        mx0 = fmaxf(mx0, __shfl_xor_sync(0xffffffffu, mx0, 1));
        mx0 = fmaxf(mx0, __shfl_xor_sync(0xffffffffu, mx0, 2));
        mx1 = fmaxf(mx1, __shfl_xor_sync(0xffffffffu, mx1, 1));
        mx1 = fmaxf(mx1, __shfl_xor_sync(0xffffffffu, mx1, 2));
        float mn0 = fmaxf(mi0, mx0), mn1 = fmaxf(mi1, mx1);
        float sc0 = ex2(mi0 - mn0), sc1 = ex2(mi1 - mn1);
        mi0 = mn0; mi1 = mn1;
#pragma unroll
        for (int nf = 0; nf < 8; nf++){
            o[nf][0] *= sc0; o[nf][1] *= sc0;
            o[nf][2] *= sc1; o[nf][3] *= sc1;
        }
        oS[0] *= sc0; oS[1] *= sc0; oS[2] *= sc1; oS[3] *= sc1;

        // ---- O += P @ V : exp fused into A-frag packing (f16x2 ex2);
        //      li accumulated by MMA vs constant all-ones B-frag ----
        uint32_t vbase = vs_sh + (uint32_t)(buf*KVBUF) + vv_off;
#pragma unroll
        for (int kc = 0; kc < 4; kc++){
            uint32_t pa[4];
            pa[0] = ex2h2(f2h2(s[2*kc][0]-mn0,   s[2*kc][1]-mn0));
            pa[1] = ex2h2(f2h2(s[2*kc][2]-mn1,   s[2*kc][3]-mn1));
            pa[2] = ex2h2(f2h2(s[2*kc+1][0]-mn0, s[2*kc+1][1]-mn0));
            pa[3] = ex2h2(f2h2(s[2*kc+1][2]-mn1, s[2*kc+1][3]-mn1));
            mma_f16(oS, pa, ONES_H2, ONES_H2);   // li partial sums
#pragma unroll
            for (int dp = 0; dp < 4; dp++){
                uint32_t vb[4];
                ldsm4t(vb, vbase + (uint32_t)(kc*16)*ROWB + dp*32);
                mma_f16(o[2*dp],   pa, vb[0], vb[1]);
                mma_f16(o[2*dp+1], pa, vb[2], vb[3]);
            }
        }
    }

    // Epilogue: li from ones-accumulator (all its cols equal the row sum)
    float inv0 = 1.f/oS[0], inv1 = 1.f/oS[2];
    int row = qt*128 + w*16 + g;
#pragma unroll
    for (int nf = 0; nf < 8; nf++){
        int col = h*DHEAD + nf*8 + t*2;
        *(uint32_t*)&outh[((size_t)(b*NN+row))*INNER + col]   =
            f2h2(o[nf][0]*inv0, o[nf][1]*inv0);
        *(uint32_t*)&outh[((size_t)(b*NN+row+8))*INNER + col] =
            f2h2(o[nf][2]*inv1, o[nf][3]*inv1);
    }
}

// ---------------------------------------------------------------------------
extern "C" void kernel_launch(void* const* d_in, const int* in_sizes, int n_in,
                              void* d_out, int out_size) {
    const float* x      = (const float*)d_in[0];
    const float* shift  = (const float*)d_in[1];
    const float* scale  = (const float*)d_in[2];
    const float* norm_w = (const float*)d_in[3];
    const float* norm_b = (const float*)d_in[4];
    const float* w_qkv  = (const float*)d_in[5];
    const float* w_out  = (const float*)d_in[6];
    const float* b_out  = (const float*)d_in[7];
    float* out = (float*)d_out;

    __half *hp, *qhp, *attnp, *wqp, *wop;
    cudaGetSymbolAddress((void**)&hp,    g_hh);
    cudaGetSymbolAddress((void**)&qhp,   g_qkvh);
    cudaGetSymbolAddress((void**)&attnp, g_attnh);
    cudaGetSymbolAddress((void**)&wqp,   g_wqkvh);
    cudaGetSymbolAddress((void**)&wop,   g_wouth);

    const int gsm_qkv = 2*128*AH_ROWB + 2*32*(128+8)*2;   // 37888
    const int gsm_out = 2*64*AH_ROWB  + 2*32*(64+8)*2;    // 19456
    cudaFuncSetAttribute((gemm_f16<128,128,2>),
                         cudaFuncAttributeMaxDynamicSharedMemorySize, gsm_qkv);
    cudaFuncSetAttribute((gemm_f16<64,64,4>),
                         cudaFuncAttributeMaxDynamicSharedMemorySize, gsm_out);
    cudaFuncSetAttribute(attn_f16,
                         cudaFuncAttributeMaxDynamicSharedMemorySize, ATTN_SMEM_BYTES);

    // Launch order keeps attention in the ncu capture slot (4th launch).
    cvt_wqkv_h<<<256, 256>>>(w_qkv, wqp, DIM*QKVN);
    ln_mod_kernel<<<TOK/8, 256>>>(x, shift, scale, norm_w, norm_b);
    gemm_f16<128,128,2><<<dim3(QKVN/128, TOK/128), 256, gsm_qkv>>>(
        hp, wqp, nullptr, nullptr, qhp, TOK, QKVN, DIM);
    attn_f16<<<dim3(8, BB*HEADS), 256, ATTN_SMEM_BYTES>>>(qhp, attnp);
    cvt_w_h<<<128, 256>>>(w_out, wop, INNER*DIM);
    gemm_f16<64,64,4><<<dim3(DIM/64, TOK/64), 256, gsm_out>>>(
        attnp, wop, b_out, out, nullptr, TOK, DIM, INNER);
}